// round 14
// baseline (speedup 1.0000x reference)
#include <cuda_runtime.h>
#include <cuda_bf16.h>
#include <math.h>

// ---------------- problem constants ----------------
#define B_SZ   256
#define T_SZ   512
#define HID    300
#define EMB    300
#define VOCAB  50000
#define NCLS   5
#define GATES  1200        // 4*HID
#define PCOLS  2400        // 2*GATES (A-part | B-part)

// recurrence tiling: 8 bt-groups x 15 u-tiles = 120 CTAs (1/SM, all resident)
#define BT     32          // batch rows per CTA
#define UT     20          // hidden units per CTA
#define RT     80          // 4 gates * UT rows per CTA
#define WSTR   302         // Wt row stride (floats), conflict-free LDS.64
#define NSLOT  15          // h chunks per step (one per producer CTA)
#define CHF    (BT * UT)   // 640 floats per chunk
#define CHB    (CHF * 4)   // 2560 bytes per chunk
#define NG     5           // chunk groups (3 chunks each), one mbarrier per group
#define GPS2   82          // gp row stride in u64

typedef unsigned long long u64;
typedef unsigned int u32;

// ---------------- f32x2 packed math (exact fp32 FMA/add semantics) -----------
__device__ __forceinline__ void ffma2(u64& d, u64 a, u64 b) {
    asm("fma.rn.f32x2 %0, %1, %2, %0;" : "+l"(d) : "l"(a), "l"(b));
}
__device__ __forceinline__ u64 add2(u64 a, u64 b) {
    u64 r; asm("add.rn.f32x2 %0, %1, %2;" : "=l"(r) : "l"(a), "l"(b)); return r;
}
__device__ __forceinline__ u64 dup2(float x) {
    u64 r; asm("mov.b64 %0, {%1, %1};" : "=l"(r) : "f"(x)); return r;
}
__device__ __forceinline__ float2 unpack2(u64 v) {
    float2 f; asm("mov.b64 {%0, %1}, %2;" : "=f"(f.x), "=f"(f.y) : "l"(v)); return f;
}
__device__ __forceinline__ float fsig(float x) {
    return __fdividef(1.f, 1.f + __expf(-x));
}

// ---------------- static device scratch (no allocations allowed) -------------
__device__ float d_P[(long long)VOCAB * PCOLS];      // 480 MB: glove @ [A|B]^T
__device__ float d_Wcat[PCOLS * EMB];                // repacked W_ih
// h mailbox: [parity][bt][producer ut][32][20]
__device__ __align__(256) float d_hG[2 * 8 * NSLOT * CHF];
__device__ float d_hsum[B_SZ * HID];                 // sum_t h_t
__device__ u32 d_arrive[8][16];                      // per-(bt, producer) flags

// ---------------- prep: repack W_ih, reset flags ------------------------------
__global__ void prep_kernel(const float* __restrict__ W_ih,
                            float* __restrict__ Wcat) {
    int i = blockIdx.x * blockDim.x + threadIdx.x;
    if (i < PCOLS * EMB) {
        int n = i / EMB, k = i % EMB;
        Wcat[i] = (n < GATES) ? W_ih[n * 600 + k]
                              : W_ih[(n - GATES) * 600 + 300 + k];
    }
    if (i < 128) ((u32*)d_arrive)[i] = 0u;
}

// ---------------- C = A @ B^T with packed f32x2 FMA (VERBATIM R12, proven) ----
#define TILE 128
#define KB   10
__global__ __launch_bounds__(256)
void sgemm_f2(const float* __restrict__ A, const float* __restrict__ B,
              float* __restrict__ C,
              int M, int N, int Klen, int lda, int ldb, int ldc) {
    __shared__ __align__(16) float As[KB][TILE + 4];
    __shared__ __align__(16) float Bs[KB][TILE + 4];

    const int m0 = blockIdx.y * TILE;
    const int n0 = blockIdx.x * TILE;
    const int tid = threadIdx.x;
    const int tx = tid & 15;
    const int ty = tid >> 4;

    u64 acc[8][4];
#pragma unroll
    for (int i = 0; i < 8; i++)
#pragma unroll
        for (int p = 0; p < 4; p++) acc[i][p] = 0ULL;

    for (int kk = 0; kk < Klen; kk += KB) {
#pragma unroll
        for (int it = 0; it < (TILE * KB) / 256; it++) {
            int idx = tid + it * 256;
            int k = idx % KB;
            int m = idx / KB;
            int gm = m0 + m;
            float v = 0.f;
            if (gm < M) v = A[(long long)gm * lda + (kk + k)];
            As[k][m] = v;
        }
#pragma unroll
        for (int it = 0; it < (TILE * KB) / 256; it++) {
            int idx = tid + it * 256;
            int k = idx % KB;
            int n = idx / KB;
            int gn = n0 + n;
            float v = 0.f;
            if (gn < N) v = B[(long long)gn * ldb + (kk + k)];
            Bs[k][n] = v;
        }
        __syncthreads();

#pragma unroll
        for (int kb = 0; kb < KB; kb++) {
            u64 ad[8], bd[4];
#pragma unroll
            for (int i = 0; i < 8; i++) ad[i] = dup2(As[kb][ty * 8 + i]);
#pragma unroll
            for (int p = 0; p < 4; p++)
                bd[p] = *(const u64*)&Bs[kb][2 * tx + 32 * p];
#pragma unroll
            for (int i = 0; i < 8; i++)
#pragma unroll
                for (int p = 0; p < 4; p++)
                    ffma2(acc[i][p], ad[i], bd[p]);
        }
        __syncthreads();
    }

#pragma unroll
    for (int i = 0; i < 8; i++) {
        int gm = m0 + ty * 8 + i;
        if (gm < M) {
#pragma unroll
            for (int p = 0; p < 4; p++) {
                int gn = n0 + 2 * tx + 32 * p;
                if (gn < N)
                    *(u64*)&C[(long long)gm * ldc + gn] = acc[i][p];
            }
        }
    }
}

// ---------------- sync + bulk-copy helpers -------------------------------------
__device__ __forceinline__ u32 ld_acq(const u32* p) {
    u32 v;
    asm volatile("ld.global.acquire.gpu.u32 %0, [%1];" : "=r"(v) : "l"(p));
    return v;
}
__device__ __forceinline__ void st_rel(u32* p, u32 v) {
    asm volatile("st.global.release.gpu.u32 [%0], %1;" :: "l"(p), "r"(v));
}
__device__ __forceinline__ u32 smem_u32(const void* p) {
    u32 a;
    asm("{ .reg .u64 t; cvta.to.shared.u64 t, %1; cvt.u32.u64 %0, t; }"
        : "=r"(a) : "l"(p));
    return a;
}
__device__ __forceinline__ void mbar_init(u32 mbar, u32 cnt) {
    asm volatile("mbarrier.init.shared.b64 [%0], %1;" :: "r"(mbar), "r"(cnt) : "memory");
}
__device__ __forceinline__ void mbar_expect_tx(u32 mbar, u32 bytes) {
    asm volatile("mbarrier.arrive.expect_tx.shared.b64 _, [%0], %1;"
                 :: "r"(mbar), "r"(bytes) : "memory");
}
__device__ __forceinline__ void bulk_cp_g2s(u32 dst, const void* src, u32 bytes, u32 mbar) {
    asm volatile("cp.async.bulk.shared::cluster.global.mbarrier::complete_tx::bytes "
                 "[%0], [%1], %2, [%3];"
                 :: "r"(dst), "l"(src), "r"(bytes), "r"(mbar) : "memory");
}
__device__ __forceinline__ void mbar_wait(u32 mbar, u32 parity) {
    asm volatile(
        "{\n\t.reg .pred P;\n\t"
        "W_%=:\n\t"
        "mbarrier.try_wait.parity.acquire.cta.shared::cta.b64 P, [%0], %1;\n\t"
        "@!P bra W_%=;\n\t}"
        :: "r"(mbar), "r"(parity) : "memory");
}
#define BAR_COMPUTE() asm volatile("bar.sync 1, 256;" ::: "memory")

// one 20-k chunk of the gates GEMM (k-pair-packed f32x2)
__device__ __forceinline__ void gemm_chunk(const float* __restrict__ hbase,
                                           const float* __restrict__ Wt,
                                           int j, int bo, int gtx, int ro,
                                           int gty, int kz, u64 acc[4][5]) {
    const float* hb = hbase + j * CHF + (bo + gtx) * UT + kz * 10;
    const float* wb = Wt + (ro + gty * 5) * WSTR + j * UT + kz * 10;
#pragma unroll
    for (int pp = 0; pp < 5; pp++) {
        int k2 = 2 * pp;
        u64 hd[4], wd[5];
#pragma unroll
        for (int i = 0; i < 4; i++)
            hd[i] = *(const u64*)(hb + i * 4 * UT + k2);
#pragma unroll
        for (int q = 0; q < 5; q++)
            wd[q] = *(const u64*)(wb + q * WSTR + k2);
#pragma unroll
        for (int i = 0; i < 4; i++)
#pragma unroll
            for (int q = 0; q < 5; q++)
                ffma2(acc[i][q], hd[i], wd[q]);
    }
}

// ---------------- self-timed persistent recurrence kernel ----------------------
// R12 skeleton + three edits: own-chunk STS short-circuit (no wait for own
// 1/15 of K), rotated group consumption (start at group ut/3 — de-convoys
// stragglers), comm warp skips own chunk (own group expects 2 chunks).
#define SM_WT   (RT * WSTR)                    // 24160 floats
#define SM_HS   (2 * NSLOT * CHF)              // 19200 floats
#define SM_GPU  (2 * BT * GPS2)                // 5248 u64
#define SM_FLOATS (SM_WT + SM_HS + 2 * SM_GPU)
#define SM_BYTES  (SM_FLOATS * 4 + 128)        // + 10 mbarriers

__global__ __launch_bounds__(288, 1)
void lstm_async(const float* __restrict__ W_hh,
                const float* __restrict__ P,
                const int* __restrict__ ids,
                const float* __restrict__ b_ih,
                const float* __restrict__ b_hh,
                float* __restrict__ hG,
                float* __restrict__ hsum) {
    extern __shared__ __align__(16) float sm[];
    float* Wt   = sm;                          // [80][302] r-major, k contiguous
    float* hsm  = sm + SM_WT;                  // [2][15][32][20]
    u64*   gp64 = (u64*)(hsm + SM_HS);         // [2 kz][32][82]

    const int tid  = threadIdx.x;
    const int lane = tid & 31;
    const int wrp  = tid >> 5;                 // 0..8
    const int bt   = blockIdx.x & 7;
    const int ut   = blockIdx.x >> 3;          // 0..14
    const int b0c  = bt * BT;
    const int u0   = ut * UT;
    const int g0   = ut / 3;                   // own chunk's group

    const u32 hsm_s   = smem_u32(hsm);
    const u32 mbar_bs = smem_u32(sm) + SM_FLOATS * 4;  // mbar(p,g) = +(p*5+g)*8

    if (tid == 0) {
#pragma unroll
        for (int m = 0; m < 2 * NG; m++) mbar_init(mbar_bs + m * 8, 1);
    }

    // =================== comm warp (warp 8): free-running =====================
    if (wrp == 8) {
        for (int tc = 0; tc < T_SZ - 1; tc++) {      // prepares steps 1..511
            const int np = (tc + 1) & 1;
            // mbar-reuse safety gate: own flag >= tc+1 implies our pointwise(tc)
            // done => our GEMM(tc) done => GEMM(tc-1) (last user of mbar[np])
            // fully consumed.
            if (lane == 0) {
                while (ld_acq(&d_arrive[bt][ut]) < (u32)(tc + 1)) {}
            }
            __syncwarp();
            if (lane < NG) {
                u32 bytes = (lane == g0) ? 2 * CHB : 3 * CHB;  // own chunk is STS'd
                mbar_expect_tx(mbar_bs + (np * NG + lane) * 8, bytes);
            }
            __syncwarp();
            // fire each chunk's bulk as soon as ITS producer flag turns
            bool done = (lane >= NSLOT) || (lane == ut);  // own chunk: local STS
            while (true) {
                if (!done && ld_acq(&d_arrive[bt][lane]) >= (u32)(tc + 1)) {
                    u32 dst = hsm_s + (u32)(np * NSLOT + lane) * CHB;
                    const float* src = hG +
                        ((size_t)(np * 8 + bt) * NSLOT + lane) * CHF;
                    bulk_cp_g2s(dst, src, CHB,
                                mbar_bs + (np * NG + lane / 3) * 8);
                    done = true;
                }
                if (__all_sync(0xFFFFFFFFu, done)) break;
            }
        }
        return;
    }

    // =================== compute warps (0..7) =================================
    for (int idx = tid; idx < RT * HID; idx += 256) {
        int r = idx / HID;
        int k = idx - r * HID;
        int g = r / UT;
        int du = r - g * UT;
        Wt[r * WSTR + k] = W_hh[(g * HID + u0 + du) * HID + k];
    }
    for (int idx = tid; idx < NSLOT * CHF; idx += 256) hsm[idx] = 0.f;

    const int kz   = wrp & 1;
    const int quad = wrp >> 1;
    const int bo   = (quad & 1) * 16;
    const int ro   = (quad >> 1) * 40;
    const int gtx  = lane & 3;                 // b = bo + gtx + 4i, i<4
    const int gty  = lane >> 2;                // r = ro + gty*5 + q, q<5

    int bl[3], duc[3];
    bool actc[3];
#pragma unroll
    for (int c = 0; c < 3; c++) {
        int cell = tid + c * 256;
        bl[c] = cell / UT;
        duc[c] = cell - bl[c] * UT;
        actc[c] = (c < 2) || (tid < 128);
    }
    float cr[3] = {0.f, 0.f, 0.f};
    float hs[3] = {0.f, 0.f, 0.f};
    float bs[3][4];
#pragma unroll
    for (int c = 0; c < 3; c++) {
#pragma unroll
        for (int g = 0; g < 4; g++) {
            int col = g * HID + u0 + duc[c];
            bs[c][g] = actc[c] ? (b_ih[col] + b_hh[col]) : 0.f;
        }
    }
    BAR_COMPUTE();   // W + zeroed h slots + mbar init visible to compute warps

    for (int t = 0; t < T_SZ; t++) {
        const int p  = t & 1;
        const int np = (t + 1) & 1;
        const u32 ph = (u32)(((t >> 1) + 1 - p) & 1);

        // ---- prefetch P gathers (overlap chunk waits + GEMM) ----
        float pfA[3][4], pfB[3][4];
#pragma unroll
        for (int c = 0; c < 3; c++) {
#pragma unroll
            for (int g = 0; g < 4; g++) { pfA[c][g] = 0.f; pfB[c][g] = 0.f; }
            if (actc[c]) {
                int row = (b0c + bl[c]) * T_SZ;
                if (t != T_SZ - 1) {           // emb[T-1] zeroed (reference quirk)
                    const float* pa = P + (long long)ids[row + t] * PCOLS
                                        + u0 + duc[c];
#pragma unroll
                    for (int g = 0; g < 4; g++) pfA[c][g] = pa[g * HID];
                }
                if (t != 0) {                  // emb_{-1} is zero padding
                    const float* pb = P + (long long)ids[row + t - 1] * PCOLS
                                        + GATES + u0 + duc[c];
#pragma unroll
                    for (int g = 0; g < 4; g++) pfB[c][g] = pb[g * HID];
                }
            }
        }

        // ---- gates GEMM: own chunk first (no wait), then rotated groups ----
        u64 acc[4][5];
#pragma unroll
        for (int i = 0; i < 4; i++)
#pragma unroll
            for (int q = 0; q < 5; q++) acc[i][q] = 0ULL;

        const float* hbase = hsm + p * (NSLOT * CHF);
        gemm_chunk(hbase, Wt, ut, bo, gtx, ro, gty, kz, acc);   // own (STS'd)

        for (int gg = 0; gg < NG; gg++) {
            int g = g0 + gg; if (g >= NG) g -= NG;
            if (t > 0) mbar_wait(mbar_bs + (p * NG + g) * 8, ph);
#pragma unroll
            for (int j3 = 0; j3 < 3; j3++) {
                const int j = g * 3 + j3;
                if (j == ut) continue;                          // already done
                gemm_chunk(hbase, Wt, j, bo, gtx, ro, gty, kz, acc);
            }
        }
        {
            u64* gp0 = gp64 + (kz * BT + bo + gtx) * GPS2 + ro + gty * 5;
#pragma unroll
            for (int i = 0; i < 4; i++)
#pragma unroll
                for (int q = 0; q < 5; q++)
                    gp0[i * 4 * GPS2 + q] = acc[i][q];
        }
        BAR_COMPUTE();   // gp complete

        // ---- fused cell update; STG mailbox (peers) + STS own slot (self) ----
        float* dst  = hG + ((size_t)(np * 8 + bt) * NSLOT + ut) * CHF;
        float* dsts = hsm + np * (NSLOT * CHF) + ut * CHF;
#pragma unroll
        for (int c = 0; c < 3; c++) {
            if (actc[c]) {
                float g4[4];
#pragma unroll
                for (int g = 0; g < 4; g++) {
                    int r = g * UT + duc[c];
                    u64 s0 = gp64[(0 * BT + bl[c]) * GPS2 + r];
                    u64 s1 = gp64[(1 * BT + bl[c]) * GPS2 + r];
                    float2 f = unpack2(add2(s0, s1));
                    g4[g] = f.x + f.y + bs[c][g] + pfA[c][g] + pfB[c][g];
                }
                float ig = fsig(g4[0]);
                float fg = fsig(g4[1]);
                float gg = 2.f * fsig(2.f * g4[2]) - 1.f;   // tanh
                float og = fsig(g4[3]);
                cr[c] = fg * cr[c] + ig * gg;
                float hv = og * (2.f * fsig(2.f * cr[c]) - 1.f);
                int off = bl[c] * UT + duc[c];
                dst[off]  = hv;     // mailbox for the 14 peers
                dsts[off] = hv;     // local copy for own next-step GEMM
                hs[c] += hv;
            }
        }
        BAR_COMPUTE();   // all STG/STS + gp consumption done

        // ---- release own chunk (peers' comm warps poll it) ----
        if (tid == 0) {
            __threadfence();
            st_rel(&d_arrive[bt][ut], (u32)(t + 1));
        }
    }

    // ---- write hidden-state sums for the classifier ----
#pragma unroll
    for (int c = 0; c < 3; c++) {
        if (actc[c])
            hsum[(b0c + bl[c]) * HID + u0 + duc[c]] = hs[c];
    }
}

// ---------------- classifier head: mean-pool -> dense(100) -> dense(5) -> LSM
__global__ void classifier(const float* __restrict__ hsum,
                           const float* __restrict__ W1, const float* __restrict__ b1,
                           const float* __restrict__ W2, const float* __restrict__ b2,
                           float* __restrict__ out) {
    int b = blockIdx.x;
    int tid = threadIdx.x;   // 128
    __shared__ float pooled[HID];
    __shared__ float l1s[100];
    __shared__ float l2s[NCLS];

    for (int i = tid; i < HID; i += blockDim.x)
        pooled[i] = hsum[b * HID + i] * (1.f / (float)T_SZ);
    __syncthreads();

    if (tid < 100) {
        float s = b1[tid];
        const float* wr = W1 + tid * HID;
#pragma unroll 4
        for (int k = 0; k < HID; k++) s = fmaf(pooled[k], wr[k], s);
        l1s[tid] = 1.f / (1.f + expf(-s));
    }
    __syncthreads();

    if (tid < NCLS) {
        float s = b2[tid];
        const float* wr = W2 + tid * 100;
#pragma unroll 4
        for (int k = 0; k < 100; k++) s = fmaf(l1s[k], wr[k], s);
        l2s[tid] = 1.f / (1.f + expf(-s));
    }
    __syncthreads();

    if (tid < NCLS) {
        float m = l2s[0];
#pragma unroll
        for (int j = 1; j < NCLS; j++) m = fmaxf(m, l2s[j]);
        float sum = 0.f;
#pragma unroll
        for (int j = 0; j < NCLS; j++) sum += expf(l2s[j] - m);
        out[b * NCLS + tid] = l2s[tid] - m - logf(sum);
    }
}

// ------------------------------ launch ---------------------------------------
extern "C" void kernel_launch(void* const* d_in, const int* in_sizes, int n_in,
                              void* d_out, int out_size) {
    const int*   ids  = nullptr;
    const float* glove = nullptr, *W_ih = nullptr, *W_hh = nullptr;
    const float* b_ih = nullptr, *b_hh = nullptr;
    const float* W1 = nullptr, *b1 = nullptr, *W2 = nullptr, *b2 = nullptr;

    for (int i = 0; i < n_in; i++) {
        switch (in_sizes[i]) {
            case B_SZ * T_SZ:      ids   = (const int*)d_in[i];   break;
            case VOCAB * EMB:      glove = (const float*)d_in[i]; break;
            case GATES * 600:      W_ih  = (const float*)d_in[i]; break;
            case GATES * HID:      W_hh  = (const float*)d_in[i]; break;
            case GATES:            if (!b_ih) b_ih = (const float*)d_in[i];
                                   else       b_hh = (const float*)d_in[i]; break;
            case 100 * HID:        W1 = (const float*)d_in[i]; break;
            case 100:              b1 = (const float*)d_in[i]; break;
            case NCLS * 100:       W2 = (const float*)d_in[i]; break;
            case NCLS:             b2 = (const float*)d_in[i]; break;
            default: break; // size-1 scalar (max_num_of_words) ignored
        }
    }
    if (!ids || !glove || !W_ih || !W_hh || !b_ih || !b_hh || !W1 || !b1 || !W2 || !b2)
        return;

    float *P, *Wcat, *hG, *hsum;
    cudaGetSymbolAddress((void**)&P,    d_P);
    cudaGetSymbolAddress((void**)&Wcat, d_Wcat);
    cudaGetSymbolAddress((void**)&hG,   d_hG);
    cudaGetSymbolAddress((void**)&hsum, d_hsum);

    static bool attr_done = false;
    if (!attr_done) {
        cudaFuncSetAttribute(lstm_async,
                             cudaFuncAttributeMaxDynamicSharedMemorySize,
                             SM_BYTES);
        attr_done = true;
    }

    // 1) repack W_ih + reset flags                  [1 node]
    prep_kernel<<<(PCOLS * EMB + 255) / 256, 256>>>(W_ih, Wcat);

    // 2) vocabulary projection P = glove @ Wcat^T   [1 node] (R12-proven kernel)
    {
        dim3 grid((PCOLS + TILE - 1) / TILE, (VOCAB + TILE - 1) / TILE, 1);
        sgemm_f2<<<grid, 256>>>(glove, Wcat, P,
                                VOCAB, PCOLS, EMB, EMB, EMB, PCOLS);
    }

    // 3) whole 512-step LSTM, self-timed dataflow   [1 node]
    lstm_async<<<120, 288, SM_BYTES>>>(W_hh, P, ids, b_ih, b_hh, hG, hsum);

    // 4) classifier head                            [1 node]
    classifier<<<B_SZ, 128>>>(hsum, W1, b1, W2, b2, (float*)d_out);
}

// round 15
// speedup vs baseline: 1.1323x; 1.1323x over previous
#include <cuda_runtime.h>
#include <cuda_bf16.h>
#include <math.h>

// ---------------- problem constants ----------------
#define B_SZ   256
#define T_SZ   512
#define HID    300
#define EMB    300
#define VOCAB  50000
#define NCLS   5
#define GATES  1200        // 4*HID
#define PCOLS  2400        // 2*GATES (A-part | B-part)

// recurrence tiling: 8 bt-groups x 15 u-tiles = 120 CTAs (1/SM, all resident)
#define BT     32          // batch rows per CTA
#define UT     20          // hidden units per CTA
#define RT     80          // 4 gates * UT rows per CTA
#define WSTR   302         // Wt row stride (floats), conflict-free LDS.64
#define NSLOT  15          // h chunks per step (one per producer CTA)
#define CHF    (BT * UT)   // 640 floats per chunk
#define CHB    (CHF * 4)   // 2560 bytes per chunk
#define NG     5           // chunk groups (3 chunks each), one mbarrier per group
#define GPS2   82          // gp row stride in u64

typedef unsigned long long u64;
typedef unsigned int u32;

// ---------------- f32x2 packed math (exact fp32 FMA/add semantics) -----------
__device__ __forceinline__ void ffma2(u64& d, u64 a, u64 b) {
    asm("fma.rn.f32x2 %0, %1, %2, %0;" : "+l"(d) : "l"(a), "l"(b));
}
__device__ __forceinline__ u64 add2(u64 a, u64 b) {
    u64 r; asm("add.rn.f32x2 %0, %1, %2;" : "=l"(r) : "l"(a), "l"(b)); return r;
}
__device__ __forceinline__ u64 dup2(float x) {
    u64 r; asm("mov.b64 %0, {%1, %1};" : "=l"(r) : "f"(x)); return r;
}
__device__ __forceinline__ float2 unpack2(u64 v) {
    float2 f; asm("mov.b64 {%0, %1}, %2;" : "=f"(f.x), "=f"(f.y) : "l"(v)); return f;
}

// ---------------- fast activations: single-MUFU tanh.approx ------------------
__device__ __forceinline__ float ftanh(float x) {
    float y; asm("tanh.approx.f32 %0, %1;" : "=f"(y) : "f"(x)); return y;
}
__device__ __forceinline__ float fsig(float x) {
    return fmaf(ftanh(0.5f * x), 0.5f, 0.5f);   // sigmoid via tanh, 1 MUFU
}

// ---------------- static device scratch (no allocations allowed) -------------
__device__ float d_P[(long long)VOCAB * PCOLS];      // 480 MB: glove @ [A|B]^T
__device__ float d_Wcat[PCOLS * EMB];                // repacked W_ih
// h mailbox: [parity][bt][producer ut][32][20]
__device__ __align__(256) float d_hG[2 * 8 * NSLOT * CHF];
__device__ float d_hsum[B_SZ * HID];                 // sum_t h_t
__device__ u32 d_arrive[8][16];                      // per-(bt, producer) flags

// ---------------- prep: repack W_ih, reset flags ------------------------------
__global__ void prep_kernel(const float* __restrict__ W_ih,
                            float* __restrict__ Wcat) {
    int i = blockIdx.x * blockDim.x + threadIdx.x;
    if (i < PCOLS * EMB) {
        int n = i / EMB, k = i % EMB;
        Wcat[i] = (n < GATES) ? W_ih[n * 600 + k]
                              : W_ih[(n - GATES) * 600 + 300 + k];
    }
    if (i < 128) ((u32*)d_arrive)[i] = 0u;
}

// ---------------- C = A @ B^T with packed f32x2 FMA (VERBATIM R12, proven) ----
#define TILE 128
#define KB   10
__global__ __launch_bounds__(256)
void sgemm_f2(const float* __restrict__ A, const float* __restrict__ B,
              float* __restrict__ C,
              int M, int N, int Klen, int lda, int ldb, int ldc) {
    __shared__ __align__(16) float As[KB][TILE + 4];
    __shared__ __align__(16) float Bs[KB][TILE + 4];

    const int m0 = blockIdx.y * TILE;
    const int n0 = blockIdx.x * TILE;
    const int tid = threadIdx.x;
    const int tx = tid & 15;
    const int ty = tid >> 4;

    u64 acc[8][4];
#pragma unroll
    for (int i = 0; i < 8; i++)
#pragma unroll
        for (int p = 0; p < 4; p++) acc[i][p] = 0ULL;

    for (int kk = 0; kk < Klen; kk += KB) {
#pragma unroll
        for (int it = 0; it < (TILE * KB) / 256; it++) {
            int idx = tid + it * 256;
            int k = idx % KB;
            int m = idx / KB;
            int gm = m0 + m;
            float v = 0.f;
            if (gm < M) v = A[(long long)gm * lda + (kk + k)];
            As[k][m] = v;
        }
#pragma unroll
        for (int it = 0; it < (TILE * KB) / 256; it++) {
            int idx = tid + it * 256;
            int k = idx % KB;
            int n = idx / KB;
            int gn = n0 + n;
            float v = 0.f;
            if (gn < N) v = B[(long long)gn * ldb + (kk + k)];
            Bs[k][n] = v;
        }
        __syncthreads();

#pragma unroll
        for (int kb = 0; kb < KB; kb++) {
            u64 ad[8], bd[4];
#pragma unroll
            for (int i = 0; i < 8; i++) ad[i] = dup2(As[kb][ty * 8 + i]);
#pragma unroll
            for (int p = 0; p < 4; p++)
                bd[p] = *(const u64*)&Bs[kb][2 * tx + 32 * p];
#pragma unroll
            for (int i = 0; i < 8; i++)
#pragma unroll
                for (int p = 0; p < 4; p++)
                    ffma2(acc[i][p], ad[i], bd[p]);
        }
        __syncthreads();
    }

#pragma unroll
    for (int i = 0; i < 8; i++) {
        int gm = m0 + ty * 8 + i;
        if (gm < M) {
#pragma unroll
            for (int p = 0; p < 4; p++) {
                int gn = n0 + 2 * tx + 32 * p;
                if (gn < N)
                    *(u64*)&C[(long long)gm * ldc + gn] = acc[i][p];
            }
        }
    }
}

// ---------------- sync + bulk-copy helpers -------------------------------------
__device__ __forceinline__ u32 ld_acq(const u32* p) {
    u32 v;
    asm volatile("ld.global.acquire.gpu.u32 %0, [%1];" : "=r"(v) : "l"(p));
    return v;
}
__device__ __forceinline__ void st_rel(u32* p, u32 v) {
    asm volatile("st.global.release.gpu.u32 [%0], %1;" :: "l"(p), "r"(v));
}
__device__ __forceinline__ u32 smem_u32(const void* p) {
    u32 a;
    asm("{ .reg .u64 t; cvta.to.shared.u64 t, %1; cvt.u32.u64 %0, t; }"
        : "=r"(a) : "l"(p));
    return a;
}
__device__ __forceinline__ void mbar_init(u32 mbar, u32 cnt) {
    asm volatile("mbarrier.init.shared.b64 [%0], %1;" :: "r"(mbar), "r"(cnt) : "memory");
}
__device__ __forceinline__ void mbar_expect_tx(u32 mbar, u32 bytes) {
    asm volatile("mbarrier.arrive.expect_tx.shared.b64 _, [%0], %1;"
                 :: "r"(mbar), "r"(bytes) : "memory");
}
__device__ __forceinline__ void bulk_cp_g2s(u32 dst, const void* src, u32 bytes, u32 mbar) {
    asm volatile("cp.async.bulk.shared::cluster.global.mbarrier::complete_tx::bytes "
                 "[%0], [%1], %2, [%3];"
                 :: "r"(dst), "l"(src), "r"(bytes), "r"(mbar) : "memory");
}
__device__ __forceinline__ void mbar_wait(u32 mbar, u32 parity) {
    asm volatile(
        "{\n\t.reg .pred P;\n\t"
        "W_%=:\n\t"
        "mbarrier.try_wait.parity.acquire.cta.shared::cta.b64 P, [%0], %1;\n\t"
        "@!P bra W_%=;\n\t}"
        :: "r"(mbar), "r"(parity) : "memory");
}
#define BAR_COMPUTE() asm volatile("bar.sync 1, 256;" ::: "memory")

// ---------------- self-timed persistent recurrence kernel ----------------------
// VERBATIM R12 structure (proven 5796us). Only deltas: tanh.approx activations
// and removal of the redundant __threadfence before the release flag
// (bar.sync gives happens-before; st.global.release publishes).
#define SM_WT   (RT * WSTR)                    // 24160 floats
#define SM_HS   (2 * NSLOT * CHF)              // 19200 floats
#define SM_GPU  (2 * BT * GPS2)                // 5248 u64
#define SM_FLOATS (SM_WT + SM_HS + 2 * SM_GPU)
#define SM_BYTES  (SM_FLOATS * 4 + 128)        // + 10 mbarriers

__global__ __launch_bounds__(288, 1)
void lstm_async(const float* __restrict__ W_hh,
                const float* __restrict__ P,
                const int* __restrict__ ids,
                const float* __restrict__ b_ih,
                const float* __restrict__ b_hh,
                float* __restrict__ hG,
                float* __restrict__ hsum) {
    extern __shared__ __align__(16) float sm[];
    float* Wt   = sm;                          // [80][302] r-major, k contiguous
    float* hsm  = sm + SM_WT;                  // [2][15][32][20]
    u64*   gp64 = (u64*)(hsm + SM_HS);         // [2 kz][32][82]

    const int tid  = threadIdx.x;
    const int lane = tid & 31;
    const int wrp  = tid >> 5;                 // 0..8
    const int bt   = blockIdx.x & 7;
    const int ut   = blockIdx.x >> 3;          // 0..14
    const int b0c  = bt * BT;
    const int u0   = ut * UT;

    const u32 hsm_s   = smem_u32(hsm);
    const u32 mbar_bs = smem_u32(sm) + SM_FLOATS * 4;  // mbar(p,g) = +(p*5+g)*8

    if (tid == 0) {
#pragma unroll
        for (int m = 0; m < 2 * NG; m++) mbar_init(mbar_bs + m * 8, 1);
    }

    // =================== comm warp (warp 8): free-running =====================
    if (wrp == 8) {
        for (int tc = 0; tc < T_SZ - 1; tc++) {      // prepares steps 1..511
            const int np = (tc + 1) & 1;
            // mbar-reuse safety gate: own flag >= tc+1 implies our pointwise(tc)
            // done => our GEMM(tc) done => GEMM(tc-1) (last user of mbar[np])
            // fully consumed. Also needed before reading own chunk via TMA.
            if (lane == 0) {
                while (ld_acq(&d_arrive[bt][ut]) < (u32)(tc + 1)) {}
            }
            __syncwarp();
            if (lane < NG)
                mbar_expect_tx(mbar_bs + (np * NG + lane) * 8, 3 * CHB);
            __syncwarp();
            // fire each chunk's bulk as soon as ITS producer flag turns
            bool done = (lane >= NSLOT);
            while (true) {
                if (!done && ld_acq(&d_arrive[bt][lane]) >= (u32)(tc + 1)) {
                    u32 dst = hsm_s + (u32)(np * NSLOT + lane) * CHB;
                    const float* src = hG +
                        ((size_t)(np * 8 + bt) * NSLOT + lane) * CHF;
                    bulk_cp_g2s(dst, src, CHB,
                                mbar_bs + (np * NG + lane / 3) * 8);
                    done = true;
                }
                if (__all_sync(0xFFFFFFFFu, done)) break;
            }
        }
        return;
    }

    // =================== compute warps (0..7) =================================
    for (int idx = tid; idx < RT * HID; idx += 256) {
        int r = idx / HID;
        int k = idx - r * HID;
        int g = r / UT;
        int du = r - g * UT;
        Wt[r * WSTR + k] = W_hh[(g * HID + u0 + du) * HID + k];
    }
    for (int idx = tid; idx < NSLOT * CHF; idx += 256) hsm[idx] = 0.f;

    const int kz   = wrp & 1;
    const int quad = wrp >> 1;
    const int bo   = (quad & 1) * 16;
    const int ro   = (quad >> 1) * 40;
    const int gtx  = lane & 3;                 // b = bo + gtx + 4i, i<4
    const int gty  = lane >> 2;                // r = ro + gty*5 + q, q<5

    int bl[3], duc[3];
    bool actc[3];
#pragma unroll
    for (int c = 0; c < 3; c++) {
        int cell = tid + c * 256;
        bl[c] = cell / UT;
        duc[c] = cell - bl[c] * UT;
        actc[c] = (c < 2) || (tid < 128);
    }
    float cr[3] = {0.f, 0.f, 0.f};
    float hs[3] = {0.f, 0.f, 0.f};
    float bs[3][4];
#pragma unroll
    for (int c = 0; c < 3; c++) {
#pragma unroll
        for (int g = 0; g < 4; g++) {
            int col = g * HID + u0 + duc[c];
            bs[c][g] = actc[c] ? (b_ih[col] + b_hh[col]) : 0.f;
        }
    }
    BAR_COMPUTE();   // W + zeroed h slots + mbar init visible to compute warps

    for (int t = 0; t < T_SZ; t++) {
        const int p  = t & 1;
        const int np = (t + 1) & 1;
        const u32 ph = (u32)(((t >> 1) + 1 - p) & 1);

        // ---- prefetch P gathers (overlap chunk waits + GEMM) ----
        float pfA[3][4], pfB[3][4];
#pragma unroll
        for (int c = 0; c < 3; c++) {
#pragma unroll
            for (int g = 0; g < 4; g++) { pfA[c][g] = 0.f; pfB[c][g] = 0.f; }
            if (actc[c]) {
                int row = (b0c + bl[c]) * T_SZ;
                if (t != T_SZ - 1) {           // emb[T-1] zeroed (reference quirk)
                    const float* pa = P + (long long)ids[row + t] * PCOLS
                                        + u0 + duc[c];
#pragma unroll
                    for (int g = 0; g < 4; g++) pfA[c][g] = pa[g * HID];
                }
                if (t != 0) {                  // emb_{-1} is zero padding
                    const float* pb = P + (long long)ids[row + t - 1] * PCOLS
                                        + GATES + u0 + duc[c];
#pragma unroll
                    for (int g = 0; g < 4; g++) pfB[c][g] = pb[g * HID];
                }
            }
        }

        // ---- gates GEMM: 32b x 80r x 300k, chunk-group pipelined ----
        u64 acc[4][5];
#pragma unroll
        for (int i = 0; i < 4; i++)
#pragma unroll
            for (int q = 0; q < 5; q++) acc[i][q] = 0ULL;

        const float* hbase = hsm + p * (NSLOT * CHF);
        for (int g = 0; g < NG; g++) {
            if (t > 0) mbar_wait(mbar_bs + (p * NG + g) * 8, ph);
#pragma unroll
            for (int j3 = 0; j3 < 3; j3++) {
                const int j = g * 3 + j3;
                const float* hb = hbase + j * CHF + (bo + gtx) * UT + kz * 10;
                const float* wb = Wt + (ro + gty * 5) * WSTR + j * UT + kz * 10;
#pragma unroll
                for (int pp = 0; pp < 5; pp++) {
                    int k2 = 2 * pp;
                    u64 hd[4], wd[5];
#pragma unroll
                    for (int i = 0; i < 4; i++)
                        hd[i] = *(const u64*)(hb + i * 4 * UT + k2);
#pragma unroll
                    for (int q = 0; q < 5; q++)
                        wd[q] = *(const u64*)(wb + q * WSTR + k2);
#pragma unroll
                    for (int i = 0; i < 4; i++)
#pragma unroll
                        for (int q = 0; q < 5; q++)
                            ffma2(acc[i][q], hd[i], wd[q]);
                }
            }
        }
        {
            u64* g0 = gp64 + (kz * BT + bo + gtx) * GPS2 + ro + gty * 5;
#pragma unroll
            for (int i = 0; i < 4; i++)
#pragma unroll
                for (int q = 0; q < 5; q++)
                    g0[i * 4 * GPS2 + q] = acc[i][q];
        }
        BAR_COMPUTE();   // gp complete

        // ---- fused cell update; STG own chunk to the mailbox ----
        float* dst = hG + ((size_t)(np * 8 + bt) * NSLOT + ut) * CHF;
#pragma unroll
        for (int c = 0; c < 3; c++) {
            if (actc[c]) {
                float g4[4];
#pragma unroll
                for (int g = 0; g < 4; g++) {
                    int r = g * UT + duc[c];
                    u64 s0 = gp64[(0 * BT + bl[c]) * GPS2 + r];
                    u64 s1 = gp64[(1 * BT + bl[c]) * GPS2 + r];
                    float2 f = unpack2(add2(s0, s1));
                    g4[g] = f.x + f.y + bs[c][g] + pfA[c][g] + pfB[c][g];
                }
                float ig = fsig(g4[0]);
                float fg = fsig(g4[1]);
                float gg = ftanh(g4[2]);
                float og = fsig(g4[3]);
                cr[c] = fg * cr[c] + ig * gg;
                float hv = og * ftanh(cr[c]);
                dst[bl[c] * UT + duc[c]] = hv;   // coalesced (cell == tid + 256c)
                hs[c] += hv;
            }
        }
        BAR_COMPUTE();   // all STGs + gp consumption done (gp reusable)

        // ---- release own chunk (single flag; consumers poll it) ----
        // bar.sync above gives happens-before from all threads' STGs to tid 0;
        // st.global.release publishes them (no extra __threadfence needed).
        if (tid == 0) {
            st_rel(&d_arrive[bt][ut], (u32)(t + 1));
        }
    }

    // ---- write hidden-state sums for the classifier ----
#pragma unroll
    for (int c = 0; c < 3; c++) {
        if (actc[c])
            hsum[(b0c + bl[c]) * HID + u0 + duc[c]] = hs[c];
    }
}

// ---------------- classifier head: mean-pool -> dense(100) -> dense(5) -> LSM
__global__ void classifier(const float* __restrict__ hsum,
                           const float* __restrict__ W1, const float* __restrict__ b1,
                           const float* __restrict__ W2, const float* __restrict__ b2,
                           float* __restrict__ out) {
    int b = blockIdx.x;
    int tid = threadIdx.x;   // 128
    __shared__ float pooled[HID];
    __shared__ float l1s[100];
    __shared__ float l2s[NCLS];

    for (int i = tid; i < HID; i += blockDim.x)
        pooled[i] = hsum[b * HID + i] * (1.f / (float)T_SZ);
    __syncthreads();

    if (tid < 100) {
        float s = b1[tid];
        const float* wr = W1 + tid * HID;
#pragma unroll 4
        for (int k = 0; k < HID; k++) s = fmaf(pooled[k], wr[k], s);
        l1s[tid] = 1.f / (1.f + expf(-s));
    }
    __syncthreads();

    if (tid < NCLS) {
        float s = b2[tid];
        const float* wr = W2 + tid * 100;
#pragma unroll 4
        for (int k = 0; k < 100; k++) s = fmaf(l1s[k], wr[k], s);
        l2s[tid] = 1.f / (1.f + expf(-s));
    }
    __syncthreads();

    if (tid < NCLS) {
        float m = l2s[0];
#pragma unroll
        for (int j = 1; j < NCLS; j++) m = fmaxf(m, l2s[j]);
        float sum = 0.f;
#pragma unroll
        for (int j = 0; j < NCLS; j++) sum += expf(l2s[j] - m);
        out[b * NCLS + tid] = l2s[tid] - m - logf(sum);
    }
}

// ------------------------------ launch ---------------------------------------
extern "C" void kernel_launch(void* const* d_in, const int* in_sizes, int n_in,
                              void* d_out, int out_size) {
    const int*   ids  = nullptr;
    const float* glove = nullptr, *W_ih = nullptr, *W_hh = nullptr;
    const float* b_ih = nullptr, *b_hh = nullptr;
    const float* W1 = nullptr, *b1 = nullptr, *W2 = nullptr, *b2 = nullptr;

    for (int i = 0; i < n_in; i++) {
        switch (in_sizes[i]) {
            case B_SZ * T_SZ:      ids   = (const int*)d_in[i];   break;
            case VOCAB * EMB:      glove = (const float*)d_in[i]; break;
            case GATES * 600:      W_ih  = (const float*)d_in[i]; break;
            case GATES * HID:      W_hh  = (const float*)d_in[i]; break;
            case GATES:            if (!b_ih) b_ih = (const float*)d_in[i];
                                   else       b_hh = (const float*)d_in[i]; break;
            case 100 * HID:        W1 = (const float*)d_in[i]; break;
            case 100:              b1 = (const float*)d_in[i]; break;
            case NCLS * 100:       W2 = (const float*)d_in[i]; break;
            case NCLS:             b2 = (const float*)d_in[i]; break;
            default: break; // size-1 scalar (max_num_of_words) ignored
        }
    }
    if (!ids || !glove || !W_ih || !W_hh || !b_ih || !b_hh || !W1 || !b1 || !W2 || !b2)
        return;

    float *P, *Wcat, *hG, *hsum;
    cudaGetSymbolAddress((void**)&P,    d_P);
    cudaGetSymbolAddress((void**)&Wcat, d_Wcat);
    cudaGetSymbolAddress((void**)&hG,   d_hG);
    cudaGetSymbolAddress((void**)&hsum, d_hsum);

    static bool attr_done = false;
    if (!attr_done) {
        cudaFuncSetAttribute(lstm_async,
                             cudaFuncAttributeMaxDynamicSharedMemorySize,
                             SM_BYTES);
        attr_done = true;
    }

    // 1) repack W_ih + reset flags                  [1 node]
    prep_kernel<<<(PCOLS * EMB + 255) / 256, 256>>>(W_ih, Wcat);

    // 2) vocabulary projection P = glove @ Wcat^T   [1 node] (R12-proven kernel)
    {
        dim3 grid((PCOLS + TILE - 1) / TILE, (VOCAB + TILE - 1) / TILE, 1);
        sgemm_f2<<<grid, 256>>>(glove, Wcat, P,
                                VOCAB, PCOLS, EMB, EMB, EMB, PCOLS);
    }

    // 3) whole 512-step LSTM, self-timed dataflow   [1 node] (R12-proven kernel)
    lstm_async<<<120, 288, SM_BYTES>>>(W_hh, P, ids, b_ih, b_hh, hG, hsum);

    // 4) classifier head                            [1 node]
    classifier<<<B_SZ, 128>>>(hsum, W1, b1, W2, b2, (float*)d_out);
}